// round 12
// baseline (speedup 1.0000x reference)
#include <cuda_runtime.h>

// bMomentumLIF: x [B=64, T=64, F=8192] fp32 -> spikes [B, T, F] fp32.
// R12: best-measured family (float2, PF=2, 64-thr blocks, one co-resident
// wave, peeled tail, select epilogue, __ldcs loads) with the LAST untested
// store policy: __stwt (write-through). Stores are full-sector 512B/warp
// write-once streams never read back -- write-through skips dirty-line
// retention in L2. Default and evict-first already A/B'd (within noise).
// Kernel is pinned at the HBM mixed R+W floor: ~268MB at ~7TB/s, SM pipes idle.

#define B_DIM 64
#define T_DIM 64
#define F_DIM 8192
#define F2    (F_DIM / 2)       // 4096 float2 lanes per (b,t) row
#define PF    2                 // prefetch depth
#define TMAIN (T_DIM - PF)      // 62 unconditional-load iterations

__global__ __launch_bounds__(64, 28)
void lif_kernel(const float2* __restrict__ x,
                const float* __restrict__ p_mom,
                const float* __restrict__ p_lamb,
                const float* __restrict__ p_th,
                float2* __restrict__ out)
{
    const int f2 = blockIdx.x * 64 + threadIdx.x;  // 0..F2-1
    const int b  = blockIdx.y;

    const float mt  = p_mom[0];
    const float lb  = p_lamb[0];
    const float th  = p_th[0];
    const float omt = 1.0f - mt;
    const float olb = 1.0f - lb;

    const float2* xp = x   + (size_t)b * T_DIM * F2 + (size_t)f2;
    float2*       op = out + (size_t)b * T_DIM * F2 + (size_t)f2;

    float2 u_last = make_float2(0.f, 0.f);
    float2 m      = make_float2(0.f, 0.f);

    float2 xi0 = __ldcs(xp);
    float2 xi1 = __ldcs(xp + F2);

    // one LIF step on xi0 -> emits spike pair into S
    #define LIF_STEP(S)                                                   \
        do {                                                              \
            {                                                             \
                float u  = fmaf(u_last.x, 0.5f, xi0.x);                   \
                float d  = u - th;                                        \
                float mn = fmaf(mt, m.x, omt * (u - u_last.x));           \
                m.x = mn;                                                 \
                float v  = fmaf(u, lb, mn * olb);                         \
                u_last.x = (d >= 0.0f) ? 0.0f : v;                        \
                (S).x    = (d >= 0.0f) ? 1.0f : 0.0f;                     \
            }                                                             \
            {                                                             \
                float u  = fmaf(u_last.y, 0.5f, xi0.y);                   \
                float d  = u - th;                                        \
                float mn = fmaf(mt, m.y, omt * (u - u_last.y));           \
                m.y = mn;                                                 \
                float v  = fmaf(u, lb, mn * olb);                         \
                u_last.y = (d >= 0.0f) ? 0.0f : v;                        \
                (S).y    = (d >= 0.0f) ? 1.0f : 0.0f;                     \
            }                                                             \
        } while (0)

    // main loop: unconditional prefetch, no predicate in hot path
    #pragma unroll 8
    for (int t = 0; t < TMAIN; ++t) {
        float2 xn = __ldcs(xp + (size_t)(t + PF) * F2);
        float2 s;
        LIF_STEP(s);
        __stwt(op + (size_t)t * F2, s);   // write-through store (R12 variable)
        xi0 = xi1;
        xi1 = xn;
    }

    // peeled tail: last PF iterations, no loads
    #pragma unroll
    for (int t = TMAIN; t < T_DIM; ++t) {
        float2 s;
        LIF_STEP(s);
        __stwt(op + (size_t)t * F2, s);
        xi0 = xi1;
    }

    #undef LIF_STEP
}

extern "C" void kernel_launch(void* const* d_in, const int* in_sizes, int n_in,
                              void* d_out, int out_size)
{
    const float2* x    = (const float2*)d_in[0];
    const float*  mom  = (const float*)d_in[1];
    const float*  lamb = (const float*)d_in[2];
    const float*  th   = (const float*)d_in[3];
    float2*       out  = (float2*)d_out;

    dim3 block(64);
    dim3 grid(F2 / 64, B_DIM);   // (64, 64) = 4096 blocks
    lif_kernel<<<grid, block>>>(x, mom, lamb, th, out);
}

// round 16
// speedup vs baseline: 1.0339x; 1.0339x over previous
#include <cuda_runtime.h>

// bMomentumLIF: x [B=64, T=64, F=8192] fp32 -> spikes [B, T, F] fp32.
// FINAL — best-measured configuration (R5, 47.168us), terminal after 12-round
// exploration:
//   - float2/thread, 64-thread blocks -> 4096 blocks = 27.7/SM, whole grid
//     co-resident in ONE wave at 32 regs (launch_bounds(64,28))
//   - 2-deep prefetch (depth 3 neutral, depth 4 wave-split regression)
//   - select-based spike epilogue (d>=0 ? ... ), __ldcs/__stcs streaming hints
//     (all 3 store policies A/B'd: within noise)
// Physics: 268MB irreducible R+W at ~7 TB/s = ~86% of HBM spec on a normal
// session = the mixed-stream DRAM floor. All SM pipes <=32%; occupancy at the
// one-wave register bound. Identical-source A/B showed session DVFS noise
// (15% on ncu) exceeds any remaining between-variant delta.

#define B_DIM 64
#define T_DIM 64
#define F_DIM 8192
#define F2    (F_DIM / 2)   // 4096 float2 lanes per (b,t) row
#define PF    2             // prefetch depth

__global__ __launch_bounds__(64, 28)
void lif_kernel(const float2* __restrict__ x,
                const float* __restrict__ p_mom,
                const float* __restrict__ p_lamb,
                const float* __restrict__ p_th,
                float2* __restrict__ out)
{
    const int f2 = blockIdx.x * 64 + threadIdx.x;  // 0..F2-1
    const int b  = blockIdx.y;

    const float mt  = p_mom[0];
    const float lb  = p_lamb[0];
    const float th  = p_th[0];
    const float omt = 1.0f - mt;
    const float olb = 1.0f - lb;

    const float2* xp = x   + (size_t)b * T_DIM * F2 + (size_t)f2;
    float2*       op = out + (size_t)b * T_DIM * F2 + (size_t)f2;

    float2 u_last = make_float2(0.f, 0.f);
    float2 m      = make_float2(0.f, 0.f);

    // 2-deep prefetch pipeline (addresses independent of the recurrence)
    float2 xi0 = __ldcs(xp);
    float2 xi1 = __ldcs(xp + F2);

    #pragma unroll 8
    for (int t = 0; t < T_DIM; ++t) {
        float2 xn;
        if (t + PF < T_DIM) xn = __ldcs(xp + (size_t)(t + PF) * F2);

        float2 s;
        // lane x
        {
            float u  = fmaf(u_last.x, 0.5f, xi0.x);
            float d  = u - th;
            float mn = fmaf(mt, m.x, omt * (u - u_last.x));
            m.x = mn;
            float v  = fmaf(u, lb, mn * olb);
            u_last.x = (d >= 0.0f) ? 0.0f : v;
            s.x      = (d >= 0.0f) ? 1.0f : 0.0f;
        }
        // lane y
        {
            float u  = fmaf(u_last.y, 0.5f, xi0.y);
            float d  = u - th;
            float mn = fmaf(mt, m.y, omt * (u - u_last.y));
            m.y = mn;
            float v  = fmaf(u, lb, mn * olb);
            u_last.y = (d >= 0.0f) ? 0.0f : v;
            s.y      = (d >= 0.0f) ? 1.0f : 0.0f;
        }

        __stcs(op + (size_t)t * F2, s);

        xi0 = xi1;
        xi1 = xn;
    }
}

extern "C" void kernel_launch(void* const* d_in, const int* in_sizes, int n_in,
                              void* d_out, int out_size)
{
    const float2* x    = (const float2*)d_in[0];
    const float*  mom  = (const float*)d_in[1];
    const float*  lamb = (const float*)d_in[2];
    const float*  th   = (const float*)d_in[3];
    float2*       out  = (float2*)d_out;

    dim3 block(64);
    dim3 grid(F2 / 64, B_DIM);   // (64, 64) = 4096 blocks
    lif_kernel<<<grid, block>>>(x, mom, lamb, th, out);
}